// round 14
// baseline (speedup 1.0000x reference)
#include <cuda_runtime.h>
#include <stdint.h>

// GridGCNNearNeighbors, R14: R13 (quantized uint8x3 prefilter + exact fp32
// confirm) with the __dp4a overload ambiguity fixed (0u accumulator).
//
// For each (b, s) centroid, emit the 32 smallest point indices with squared
// distance <= 0.2^2 (reference semantics), padding with the first hit.
// Filter: lb2 = sum(max(|dq|-1,0)^2) <= 2700  (real d^2 >= lb2/65536; reject
// implies d^2 >= 0.0412 > THR + fp32 rounding margin -> provably transparent).
//
// Inputs identified by element count (harness delivers int64 as int32):
//   pos        float32 [8, 8192, 3]  -> 196608 elements (unique)
//   centroids  int32   [8, 2048]     -> 16384 elements (unique)
// Output: float32 [8, 2048, 32] (indices stored as floats, exact <= 8192)

namespace {
constexpr int Bb = 8;
constexpr int Nn = 8192;
constexpr int Ss = 2048;
constexpr int Kk = 32;
constexpr float THR = 0.04f;        // (float)(0.2**2)
constexpr unsigned LB2_MAX = 2700u; // integer filter threshold (conservative)
}

// Exact plane {x,y,z,|p|^2} (1 MB) + packed 8-bit cells (256 KB)
__device__ __align__(16) float4 g_p[Bb * Nn];
__device__ unsigned g_q[Bb * Nn];

__global__ __launch_bounds__(256)
void soa_transpose_kernel(const float* __restrict__ pos) {
    const int i = blockIdx.x * blockDim.x + threadIdx.x;
    if (i >= Bb * Nn) return;
    const float* p = pos + (size_t)i * 3;
    const float x = p[0], y = p[1], z = p[2];
    g_p[i] = make_float4(x, y, z, x * x + y * y + z * z);
    const unsigned qx = min(255, (int)(x * 256.0f));
    const unsigned qy = min(255, (int)(y * 256.0f));
    const unsigned qz = min(255, (int)(z * 256.0f));
    g_q[i] = qx | (qy << 8) | (qz << 16);
}

__global__ __launch_bounds__(64, 24)
void gridgcn_knn_kernel(const int* __restrict__ centroids,
                        float* __restrict__ out) {
    const int warp_id = (blockIdx.x << 1) | (threadIdx.x >> 5);
    const int lane = threadIdx.x & 31;
    if (warp_id >= Bb * Ss) return;

    const int b = warp_id >> 11;          // / 2048
    const int c = centroids[warp_id] & (Nn - 1);
    const float4* __restrict__ pp = g_p + b * Nn;
    const unsigned* __restrict__ qq = g_q + b * Nn;

    // Center: exact coords + quantized cell (warp-uniform broadcasts)
    const float4 cp = pp[c];
    const float cx = cp.x, cy = cp.y, cz = cp.z;
    const float sc = cx * cx + cy * cy + cz * cz;  // same form as reference
    const unsigned qc = qq[c];

    float* __restrict__ o = out + (size_t)warp_id * Kk;

    int have = 0;
    int first_idx = Nn;
    const unsigned below = (1u << lane) - 1u;
    const unsigned mybit = 1u << lane;
    bool done = false;

    #pragma unroll 1
    for (int base = 0; base < Nn && !done; base += 256) {
        // Packed-cell loads: 8 coalesced LDG.32 (4 B/point hot stream)
        unsigned q[8];
        #pragma unroll
        for (int k = 0; k < 8; k++) q[k] = qq[base + 32 * k + lane];

        // Conservative integer lower-bound filter (3 SIMD ops/point)
        unsigned cand[8];
        #pragma unroll
        for (int k = 0; k < 8; k++) {
            const unsigned t = __vsubus4(__vabsdiffu4(q[k], qc), 0x00010101u);
            const unsigned lb2 = __dp4a(t, t, 0u);
            cand[k] = __ballot_sync(0xffffffffu, lb2 <= LB2_MAX);
        }

        if (cand[0] | cand[1] | cand[2] | cand[3] |
            cand[4] | cand[5] | cand[6] | cand[7]) {
            #pragma unroll
            for (int k = 0; k < 8; k++) {
                if (!cand[k]) continue;               // warp-uniform
                // Exact confirm on candidates only (identical d^2 expression)
                bool hit = false;
                if (cand[k] & mybit) {
                    const float4 p = pp[base + 32 * k + lane];
                    const float d2 = sc + p.w - 2.0f * (cx * p.x + cy * p.y + cz * p.z);
                    hit = (d2 <= THR);
                }
                const unsigned me = __ballot_sync(0xffffffffu, hit);
                if (me) {
                    if (have == 0) first_idx = base + 32 * k + __ffs(me) - 1;
                    const int s = have + __popc(me & below);
                    if ((me & mybit) && s < Kk) o[s] = (float)(base + 32 * k + lane);
                    have += __popc(me);
                    if (have >= Kk) { done = true; break; }
                }
            }
        }
    }

    // Pad tail with group_first (warp-uniform value)
    const float fpad = (float)first_idx;
    for (int i = have + lane; i < Kk; i += 32) o[i] = fpad;
}

extern "C" void kernel_launch(void* const* d_in, const int* in_sizes, int n_in,
                              void* d_out, int out_size) {
    (void)out_size;
    const float* pos = nullptr;
    const int* centroids = nullptr;
    for (int i = 0; i < n_in; i++) {
        if (in_sizes[i] == Bb * Nn * 3)      pos = (const float*)d_in[i];
        else if (in_sizes[i] == Bb * Ss)     centroids = (const int*)d_in[i];
    }
    float* out = (float*)d_out;

    soa_transpose_kernel<<<(Bb * Nn + 255) / 256, 256>>>(pos);

    const int total_warps = Bb * Ss;           // 16384
    const int threads = 64;                    // 2 warps/block (R10 shape)
    const int blocks = total_warps / 2;        // 8192
    gridgcn_knn_kernel<<<blocks, threads>>>(centroids, out);
}

// round 15
// speedup vs baseline: 1.0119x; 1.0119x over previous
#include <cuda_runtime.h>
#include <stdint.h>

// GridGCNNearNeighbors, R15: R12 scan core (fused float4, 256-pt tiles,
// 1 centroid/warp) + LPT processing order via 16-bucket cost permutation.
//
// For each (b, s) centroid, emit the 32 smallest point indices with squared
// distance <= 0.2^2 (reference semantics), padding with the first hit.
//
// Inputs identified by element count (harness delivers int64 as int32):
//   pos        float32 [8, 8192, 3]  -> 196608 elements (unique)
//   centroids  int32   [8, 2048]     -> 16384 elements (unique)
// Output: float32 [8, 2048, 32] (indices stored as floats, exact <= 8192)

namespace {
constexpr int Bb = 8;
constexpr int Nn = 8192;
constexpr int Ss = 2048;
constexpr int Kk = 32;
constexpr float THR = 0.04f;  // (float)(0.2**2)
constexpr int TOTAL = Bb * Ss;
constexpr int NBUCKET = 16;
}

// Fused SoA plane {x,y,z,|p|^2} (1 MB) + LPT permutation scratch
__device__ __align__(16) float4 g_p[Bb * Nn];
__device__ int g_order[TOTAL];
__device__ unsigned char g_key[TOTAL];

__global__ __launch_bounds__(256)
void soa_transpose_kernel(const float* __restrict__ pos) {
    const int i = blockIdx.x * blockDim.x + threadIdx.x;
    if (i >= Bb * Nn) return;
    const float* p = pos + (size_t)i * 3;
    const float x = p[0], y = p[1], z = p[2];
    g_p[i] = make_float4(x, y, z, x * x + y * y + z * z);
}

// One block: bucket centroids by estimated scan cost (longest first) and emit
// the processing permutation. Intra-bucket order is atomic-timing dependent,
// but per-centroid outputs are independent of processing order.
__global__ __launch_bounds__(1024)
void order_kernel(const int* __restrict__ centroids) {
    __shared__ int hist[NBUCKET];
    __shared__ int cur[NBUCKET];
    const int tid = threadIdx.x;
    if (tid < NBUCKET) hist[tid] = 0;
    __syncthreads();

    for (int i = tid; i < TOTAL; i += 1024) {
        const int b = i >> 11;
        const int c = centroids[i] & (Nn - 1);
        const float4 cp = g_p[b * Nn + c];
        // per-axis coverage of the radius-0.2 ball inside the unit cube
        const float covx = fminf(cp.x + 0.2f, 1.0f) - fmaxf(cp.x - 0.2f, 0.0f);
        const float covy = fminf(cp.y + 0.2f, 1.0f) - fmaxf(cp.y - 0.2f, 0.0f);
        const float covz = fminf(cp.z + 0.2f, 1.0f) - fmaxf(cp.z - 0.2f, 0.0f);
        const float key = covx * covy * covz;       // in [0.008, 0.064]
        int k = (int)((key - 0.008f) * (16.0f / 0.056f));
        k = max(0, min(NBUCKET - 1, k));            // small key = long scan = bucket 0
        g_key[i] = (unsigned char)k;
        atomicAdd(&hist[k], 1);
    }
    __syncthreads();

    if (tid == 0) {
        int run = 0;
        for (int k = 0; k < NBUCKET; k++) { cur[k] = run; run += hist[k]; }
    }
    __syncthreads();

    for (int i = tid; i < TOTAL; i += 1024) {
        const int slot = atomicAdd(&cur[g_key[i]], 1);
        g_order[slot] = i;
    }
}

__global__ __launch_bounds__(64, 20)
void gridgcn_knn_kernel(const int* __restrict__ centroids,
                        float* __restrict__ out) {
    const int warp_id = (blockIdx.x << 1) | (threadIdx.x >> 5);
    const int lane = threadIdx.x & 31;
    if (warp_id >= TOTAL) return;

    const int cid = g_order[warp_id];     // LPT order: longest scans first
    const int b = cid >> 11;              // / 2048
    const int c = centroids[cid] & (Nn - 1);
    const float4* __restrict__ pp = g_p + b * Nn;

    const float4 cp = pp[c];
    const float cx = cp.x, cy = cp.y, cz = cp.z;
    // Same expansion form as reference: ||c||^2 + ||p||^2 - 2 c.p
    const float sc = cx * cx + cy * cy + cz * cz;

    float* __restrict__ o = out + (size_t)cid * Kk;

    int have = 0;
    int first_idx = Nn;
    const unsigned below = (1u << lane) - 1u;
    const unsigned mybit = 1u << lane;

    #pragma unroll 1
    for (int base = 0; base < Nn; base += 256) {
        // Eight independent coalesced LDG.128 issued back-to-back (MLP 8)
        const float4 p0 = pp[base + lane];
        const float4 p1 = pp[base + 32 + lane];
        const float4 p2 = pp[base + 64 + lane];
        const float4 p3 = pp[base + 96 + lane];
        const float4 p4 = pp[base + 128 + lane];
        const float4 p5 = pp[base + 160 + lane];
        const float4 p6 = pp[base + 192 + lane];
        const float4 p7 = pp[base + 224 + lane];

        const float d20 = sc + p0.w - 2.0f * (cx * p0.x + cy * p0.y + cz * p0.z);
        const float d21 = sc + p1.w - 2.0f * (cx * p1.x + cy * p1.y + cz * p1.z);
        const float d22 = sc + p2.w - 2.0f * (cx * p2.x + cy * p2.y + cz * p2.z);
        const float d23 = sc + p3.w - 2.0f * (cx * p3.x + cy * p3.y + cz * p3.z);
        const float d24 = sc + p4.w - 2.0f * (cx * p4.x + cy * p4.y + cz * p4.z);
        const float d25 = sc + p5.w - 2.0f * (cx * p5.x + cy * p5.y + cz * p5.z);
        const float d26 = sc + p6.w - 2.0f * (cx * p6.x + cy * p6.y + cz * p6.z);
        const float d27 = sc + p7.w - 2.0f * (cx * p7.x + cy * p7.y + cz * p7.z);

        // m_k bit l  <->  point  base + 32*k + l
        const unsigned m0 = __ballot_sync(0xffffffffu, d20 <= THR);
        const unsigned m1 = __ballot_sync(0xffffffffu, d21 <= THR);
        const unsigned m2 = __ballot_sync(0xffffffffu, d22 <= THR);
        const unsigned m3 = __ballot_sync(0xffffffffu, d23 <= THR);
        const unsigned m4 = __ballot_sync(0xffffffffu, d24 <= THR);
        const unsigned m5 = __ballot_sync(0xffffffffu, d25 <= THR);
        const unsigned m6 = __ballot_sync(0xffffffffu, d26 <= THR);
        const unsigned m7 = __ballot_sync(0xffffffffu, d27 <= THR);

        if (m0 | m1 | m2 | m3 | m4 | m5 | m6 | m7) {
            if (have == 0) {
                if (m0)      first_idx = base + __ffs(m0) - 1;
                else if (m1) first_idx = base + 32 + __ffs(m1) - 1;
                else if (m2) first_idx = base + 64 + __ffs(m2) - 1;
                else if (m3) first_idx = base + 96 + __ffs(m3) - 1;
                else if (m4) first_idx = base + 128 + __ffs(m4) - 1;
                else if (m5) first_idx = base + 160 + __ffs(m5) - 1;
                else if (m6) first_idx = base + 192 + __ffs(m6) - 1;
                else         first_idx = base + 224 + __ffs(m7) - 1;
            }
            int cum = have;
            const unsigned ms[8] = {m0, m1, m2, m3, m4, m5, m6, m7};
            #pragma unroll
            for (int k = 0; k < 8; k++) {
                const int s = cum + __popc(ms[k] & below);
                if ((ms[k] & mybit) && s < Kk) o[s] = (float)(base + 32 * k + lane);
                cum += __popc(ms[k]);
            }
            have = cum;
            if (have >= Kk) break;
        }
    }

    // Pad tail with group_first (warp-uniform value)
    const float fpad = (float)first_idx;
    for (int i = have + lane; i < Kk; i += 32) o[i] = fpad;
}

extern "C" void kernel_launch(void* const* d_in, const int* in_sizes, int n_in,
                              void* d_out, int out_size) {
    (void)out_size;
    const float* pos = nullptr;
    const int* centroids = nullptr;
    for (int i = 0; i < n_in; i++) {
        if (in_sizes[i] == Bb * Nn * 3)      pos = (const float*)d_in[i];
        else if (in_sizes[i] == Bb * Ss)     centroids = (const int*)d_in[i];
    }
    float* out = (float*)d_out;

    soa_transpose_kernel<<<(Bb * Nn + 255) / 256, 256>>>(pos);
    order_kernel<<<1, 1024>>>(centroids);

    const int total_warps = TOTAL;             // 16384
    const int threads = 64;                    // 2 warps/block (proven shape)
    const int blocks = total_warps / 2;        // 8192
    gridgcn_knn_kernel<<<blocks, threads>>>(centroids, out);
}

// round 16
// speedup vs baseline: 1.2241x; 1.2097x over previous
#include <cuda_runtime.h>
#include <stdint.h>

// GridGCNNearNeighbors, R16: two-phase scan. Phase 1 = R12 core capped at
// 4096 points; unfinished (low-hit) centroids are rescued in phase 2 by a
// 4-warp block splitting [4096, 8192). Natural batch-major order preserved.
//
// For each (b, s) centroid, emit the 32 smallest point indices with squared
// distance <= 0.2^2 (reference semantics), padding with the first hit.
//
// Inputs identified by element count (harness delivers int64 as int32):
//   pos        float32 [8, 8192, 3]  -> 196608 elements (unique)
//   centroids  int32   [8, 2048]     -> 16384 elements (unique)
// Output: float32 [8, 2048, 32] (indices stored as floats, exact <= 8192)

namespace {
constexpr int Bb = 8;
constexpr int Nn = 8192;
constexpr int Ss = 2048;
constexpr int Kk = 32;
constexpr float THR = 0.04f;  // (float)(0.2**2)
constexpr int TOTAL = Bb * Ss;
constexpr int CAP = 4096;     // phase-1 point cap (16 tiles of 256)
}

__device__ __align__(16) float4 g_p[Bb * Nn];
__device__ int g_rescue[TOTAL];
__device__ int g_have[TOTAL];
__device__ int g_first[TOTAL];
__device__ int g_rn;

__global__ __launch_bounds__(256)
void soa_transpose_kernel(const float* __restrict__ pos) {
    const int i = blockIdx.x * blockDim.x + threadIdx.x;
    if (i == 0) g_rn = 0;  // deterministic per-launch reset (kernel order guarantees visibility)
    if (i >= Bb * Nn) return;
    const float* p = pos + (size_t)i * 3;
    const float x = p[0], y = p[1], z = p[2];
    g_p[i] = make_float4(x, y, z, x * x + y * y + z * z);
}

// Process one 256-point tile; returns updated 'have'. Hits written via cb.
// (Kept as a macro-like inline to guarantee the exact same d2 expression.)
__global__ __launch_bounds__(64, 20)
void gridgcn_phase1(const int* __restrict__ centroids,
                    float* __restrict__ out) {
    const int warp_id = (blockIdx.x << 1) | (threadIdx.x >> 5);
    const int lane = threadIdx.x & 31;
    if (warp_id >= TOTAL) return;

    const int b = warp_id >> 11;
    const int c = centroids[warp_id] & (Nn - 1);
    const float4* __restrict__ pp = g_p + b * Nn;

    const float4 cp = pp[c];
    const float cx = cp.x, cy = cp.y, cz = cp.z;
    const float sc = cx * cx + cy * cy + cz * cz;  // same form as reference

    float* __restrict__ o = out + (size_t)warp_id * Kk;

    int have = 0;
    int first_idx = Nn;
    const unsigned below = (1u << lane) - 1u;
    const unsigned mybit = 1u << lane;

    #pragma unroll 1
    for (int base = 0; base < CAP; base += 256) {
        const float4 p0 = pp[base + lane];
        const float4 p1 = pp[base + 32 + lane];
        const float4 p2 = pp[base + 64 + lane];
        const float4 p3 = pp[base + 96 + lane];
        const float4 p4 = pp[base + 128 + lane];
        const float4 p5 = pp[base + 160 + lane];
        const float4 p6 = pp[base + 192 + lane];
        const float4 p7 = pp[base + 224 + lane];

        const float d20 = sc + p0.w - 2.0f * (cx * p0.x + cy * p0.y + cz * p0.z);
        const float d21 = sc + p1.w - 2.0f * (cx * p1.x + cy * p1.y + cz * p1.z);
        const float d22 = sc + p2.w - 2.0f * (cx * p2.x + cy * p2.y + cz * p2.z);
        const float d23 = sc + p3.w - 2.0f * (cx * p3.x + cy * p3.y + cz * p3.z);
        const float d24 = sc + p4.w - 2.0f * (cx * p4.x + cy * p4.y + cz * p4.z);
        const float d25 = sc + p5.w - 2.0f * (cx * p5.x + cy * p5.y + cz * p5.z);
        const float d26 = sc + p6.w - 2.0f * (cx * p6.x + cy * p6.y + cz * p6.z);
        const float d27 = sc + p7.w - 2.0f * (cx * p7.x + cy * p7.y + cz * p7.z);

        const unsigned m0 = __ballot_sync(0xffffffffu, d20 <= THR);
        const unsigned m1 = __ballot_sync(0xffffffffu, d21 <= THR);
        const unsigned m2 = __ballot_sync(0xffffffffu, d22 <= THR);
        const unsigned m3 = __ballot_sync(0xffffffffu, d23 <= THR);
        const unsigned m4 = __ballot_sync(0xffffffffu, d24 <= THR);
        const unsigned m5 = __ballot_sync(0xffffffffu, d25 <= THR);
        const unsigned m6 = __ballot_sync(0xffffffffu, d26 <= THR);
        const unsigned m7 = __ballot_sync(0xffffffffu, d27 <= THR);

        if (m0 | m1 | m2 | m3 | m4 | m5 | m6 | m7) {
            if (have == 0) {
                if (m0)      first_idx = base + __ffs(m0) - 1;
                else if (m1) first_idx = base + 32 + __ffs(m1) - 1;
                else if (m2) first_idx = base + 64 + __ffs(m2) - 1;
                else if (m3) first_idx = base + 96 + __ffs(m3) - 1;
                else if (m4) first_idx = base + 128 + __ffs(m4) - 1;
                else if (m5) first_idx = base + 160 + __ffs(m5) - 1;
                else if (m6) first_idx = base + 192 + __ffs(m6) - 1;
                else         first_idx = base + 224 + __ffs(m7) - 1;
            }
            int cum = have;
            const unsigned ms[8] = {m0, m1, m2, m3, m4, m5, m6, m7};
            #pragma unroll
            for (int k = 0; k < 8; k++) {
                const int s = cum + __popc(ms[k] & below);
                if ((ms[k] & mybit) && s < Kk) o[s] = (float)(base + 32 * k + lane);
                cum += __popc(ms[k]);
            }
            have = cum;
            if (have >= Kk) break;
        }
    }

    if (have >= Kk) return;  // done; all 32 slots written

    // Unfinished: enqueue for phase 2 (partial hits already in o[0..have))
    g_have[warp_id] = have;
    g_first[warp_id] = first_idx;
    if (lane == 0) {
        const int slot = atomicAdd(&g_rn, 1);
        g_rescue[slot] = warp_id;
    }
}

__global__ __launch_bounds__(128)
void gridgcn_phase2(const int* __restrict__ centroids,
                    float* __restrict__ out) {
    __shared__ int s_hits[4][Kk];
    __shared__ int s_cnt[4];
    const int w = threadIdx.x >> 5;
    const int lane = threadIdx.x & 31;
    const unsigned below = (1u << lane) - 1u;
    const unsigned mybit = 1u << lane;
    const int nr = g_rn;

    for (int j = blockIdx.x; j < nr; j += gridDim.x) {
        const int cid = g_rescue[j];
        const int b = cid >> 11;
        const int c = centroids[cid] & (Nn - 1);
        const float4* __restrict__ pp = g_p + b * Nn;

        const float4 cp = pp[c];
        const float cx = cp.x, cy = cp.y, cz = cp.z;
        const float sc = cx * cx + cy * cy + cz * cz;  // same form as reference

        // Warp w scans [CAP + 1024*w, CAP + 1024*(w+1)) collecting <=32 hits
        int cnt = 0;
        const int r0 = CAP + (w << 10);
        #pragma unroll 1
        for (int base = r0; base < r0 + 1024; base += 256) {
            const float4 p0 = pp[base + lane];
            const float4 p1 = pp[base + 32 + lane];
            const float4 p2 = pp[base + 64 + lane];
            const float4 p3 = pp[base + 96 + lane];
            const float4 p4 = pp[base + 128 + lane];
            const float4 p5 = pp[base + 160 + lane];
            const float4 p6 = pp[base + 192 + lane];
            const float4 p7 = pp[base + 224 + lane];

            const float d20 = sc + p0.w - 2.0f * (cx * p0.x + cy * p0.y + cz * p0.z);
            const float d21 = sc + p1.w - 2.0f * (cx * p1.x + cy * p1.y + cz * p1.z);
            const float d22 = sc + p2.w - 2.0f * (cx * p2.x + cy * p2.y + cz * p2.z);
            const float d23 = sc + p3.w - 2.0f * (cx * p3.x + cy * p3.y + cz * p3.z);
            const float d24 = sc + p4.w - 2.0f * (cx * p4.x + cy * p4.y + cz * p4.z);
            const float d25 = sc + p5.w - 2.0f * (cx * p5.x + cy * p5.y + cz * p5.z);
            const float d26 = sc + p6.w - 2.0f * (cx * p6.x + cy * p6.y + cz * p6.z);
            const float d27 = sc + p7.w - 2.0f * (cx * p7.x + cy * p7.y + cz * p7.z);

            const unsigned mm[8] = {
                __ballot_sync(0xffffffffu, d20 <= THR),
                __ballot_sync(0xffffffffu, d21 <= THR),
                __ballot_sync(0xffffffffu, d22 <= THR),
                __ballot_sync(0xffffffffu, d23 <= THR),
                __ballot_sync(0xffffffffu, d24 <= THR),
                __ballot_sync(0xffffffffu, d25 <= THR),
                __ballot_sync(0xffffffffu, d26 <= THR),
                __ballot_sync(0xffffffffu, d27 <= THR)};

            #pragma unroll
            for (int k = 0; k < 8; k++) {
                const int s = cnt + __popc(mm[k] & below);
                if ((mm[k] & mybit) && s < Kk) s_hits[w][s] = base + 32 * k + lane;
                cnt += __popc(mm[k]);
            }
            if (cnt >= Kk) break;
        }
        if (lane == 0) s_cnt[w] = min(cnt, Kk);
        __syncthreads();

        // Warp 0 merges: phase-1 partials (already in out) then ranges in order
        if (w == 0) {
            const int have0 = g_have[cid];
            float* __restrict__ o = out + (size_t)cid * Kk;
            int off = have0;
            #pragma unroll
            for (int ww = 0; ww < 4; ww++) {
                const int cw = s_cnt[ww];
                const int s = off + lane;
                if (lane < cw && s < Kk) o[s] = (float)s_hits[ww][lane];
                off += cw;
            }
            int fi = g_first[cid];
            if (have0 == 0) {
                if (s_cnt[0] > 0)      fi = s_hits[0][0];
                else if (s_cnt[1] > 0) fi = s_hits[1][0];
                else if (s_cnt[2] > 0) fi = s_hits[2][0];
                else if (s_cnt[3] > 0) fi = s_hits[3][0];
            }
            const int total = min(off, Kk);
            const float fpad = (float)fi;
            for (int i = total + lane; i < Kk; i += 32) o[i] = fpad;
        }
        __syncthreads();
    }
}

extern "C" void kernel_launch(void* const* d_in, const int* in_sizes, int n_in,
                              void* d_out, int out_size) {
    (void)out_size;
    const float* pos = nullptr;
    const int* centroids = nullptr;
    for (int i = 0; i < n_in; i++) {
        if (in_sizes[i] == Bb * Nn * 3)      pos = (const float*)d_in[i];
        else if (in_sizes[i] == Bb * Ss)     centroids = (const int*)d_in[i];
    }
    float* out = (float*)d_out;

    soa_transpose_kernel<<<(Bb * Nn + 255) / 256, 256>>>(pos);
    gridgcn_phase1<<<TOTAL / 2, 64>>>(centroids, out);
    gridgcn_phase2<<<2048, 128>>>(centroids, out);
}

// round 17
// speedup vs baseline: 1.2511x; 1.0221x over previous
#include <cuda_runtime.h>
#include <stdint.h>

// GridGCNNearNeighbors, R17: R12 scan core verbatim (fused float4{x,y,z,|p|^2},
// 256-pt tiles, 1 centroid/warp, 8192x64 grid) + fast transpose (4 points per
// thread via 3 aligned float4 loads -> BW-bound instead of latency-bound).
//
// For each (b, s) centroid, emit the 32 smallest point indices with squared
// distance <= 0.2^2 (reference semantics), padding with the first hit.
//
// Inputs identified by element count (harness delivers int64 as int32):
//   pos        float32 [8, 8192, 3]  -> 196608 elements (unique)
//   centroids  int32   [8, 2048]     -> 16384 elements (unique)
// Output: float32 [8, 2048, 32] (indices stored as floats, exact <= 8192)

namespace {
constexpr int Bb = 8;
constexpr int Nn = 8192;
constexpr int Ss = 2048;
constexpr int Kk = 32;
constexpr float THR = 0.04f;  // (float)(0.2**2)
constexpr int TOTAL = Bb * Ss;
constexpr int NPTS = Bb * Nn;            // 65536 points
constexpr int TP_THREADS = NPTS / 4;     // 4 points per thread -> 16384 threads
}

// Fused SoA plane: one float4 {x, y, z, |p|^2} per point (1 MB static scratch)
__device__ __align__(16) float4 g_p[Bb * Nn];

__global__ __launch_bounds__(256)
void soa_transpose_kernel(const float4* __restrict__ pos4) {
    const int t = blockIdx.x * blockDim.x + threadIdx.x;
    if (t >= TP_THREADS) return;
    // 4 points = 12 floats = 3 aligned float4 loads (fully coalesced, MLP 3)
    const float4 A = pos4[3 * t + 0];  // x0 y0 z0 x1
    const float4 B = pos4[3 * t + 1];  // y1 z1 x2 y2
    const float4 C = pos4[3 * t + 2];  // z2 x3 y3 z3
    const int o = 4 * t;
    g_p[o + 0] = make_float4(A.x, A.y, A.z, A.x * A.x + A.y * A.y + A.z * A.z);
    g_p[o + 1] = make_float4(A.w, B.x, B.y, A.w * A.w + B.x * B.x + B.y * B.y);
    g_p[o + 2] = make_float4(B.z, B.w, C.x, B.z * B.z + B.w * B.w + C.x * C.x);
    g_p[o + 3] = make_float4(C.y, C.z, C.w, C.y * C.y + C.z * C.z + C.w * C.w);
}

__global__ __launch_bounds__(64, 20)
void gridgcn_knn_kernel(const int* __restrict__ centroids,
                        float* __restrict__ out) {
    const int warp_id = (blockIdx.x << 1) | (threadIdx.x >> 5);
    const int lane = threadIdx.x & 31;
    if (warp_id >= TOTAL) return;

    const int b = warp_id >> 11;          // / 2048
    const int c = centroids[warp_id] & (Nn - 1);
    const float4* __restrict__ pp = g_p + b * Nn;

    // Center coordinates (warp-uniform broadcast; same bits as original pos)
    const float4 cp = pp[c];
    const float cx = cp.x, cy = cp.y, cz = cp.z;
    // Same expansion form as reference: ||c||^2 + ||p||^2 - 2 c.p
    const float sc = cx * cx + cy * cy + cz * cz;

    float* __restrict__ o = out + (size_t)warp_id * Kk;

    int have = 0;
    int first_idx = Nn;
    const unsigned below = (1u << lane) - 1u;
    const unsigned mybit = 1u << lane;

    #pragma unroll 1
    for (int base = 0; base < Nn; base += 256) {
        // Eight independent coalesced LDG.128 issued back-to-back (MLP 8)
        const float4 p0 = pp[base + lane];
        const float4 p1 = pp[base + 32 + lane];
        const float4 p2 = pp[base + 64 + lane];
        const float4 p3 = pp[base + 96 + lane];
        const float4 p4 = pp[base + 128 + lane];
        const float4 p5 = pp[base + 160 + lane];
        const float4 p6 = pp[base + 192 + lane];
        const float4 p7 = pp[base + 224 + lane];

        const float d20 = sc + p0.w - 2.0f * (cx * p0.x + cy * p0.y + cz * p0.z);
        const float d21 = sc + p1.w - 2.0f * (cx * p1.x + cy * p1.y + cz * p1.z);
        const float d22 = sc + p2.w - 2.0f * (cx * p2.x + cy * p2.y + cz * p2.z);
        const float d23 = sc + p3.w - 2.0f * (cx * p3.x + cy * p3.y + cz * p3.z);
        const float d24 = sc + p4.w - 2.0f * (cx * p4.x + cy * p4.y + cz * p4.z);
        const float d25 = sc + p5.w - 2.0f * (cx * p5.x + cy * p5.y + cz * p5.z);
        const float d26 = sc + p6.w - 2.0f * (cx * p6.x + cy * p6.y + cz * p6.z);
        const float d27 = sc + p7.w - 2.0f * (cx * p7.x + cy * p7.y + cz * p7.z);

        // m_k bit l  <->  point  base + 32*k + l
        const unsigned m0 = __ballot_sync(0xffffffffu, d20 <= THR);
        const unsigned m1 = __ballot_sync(0xffffffffu, d21 <= THR);
        const unsigned m2 = __ballot_sync(0xffffffffu, d22 <= THR);
        const unsigned m3 = __ballot_sync(0xffffffffu, d23 <= THR);
        const unsigned m4 = __ballot_sync(0xffffffffu, d24 <= THR);
        const unsigned m5 = __ballot_sync(0xffffffffu, d25 <= THR);
        const unsigned m6 = __ballot_sync(0xffffffffu, d26 <= THR);
        const unsigned m7 = __ballot_sync(0xffffffffu, d27 <= THR);

        if (m0 | m1 | m2 | m3 | m4 | m5 | m6 | m7) {
            if (have == 0) {
                if (m0)      first_idx = base + __ffs(m0) - 1;
                else if (m1) first_idx = base + 32 + __ffs(m1) - 1;
                else if (m2) first_idx = base + 64 + __ffs(m2) - 1;
                else if (m3) first_idx = base + 96 + __ffs(m3) - 1;
                else if (m4) first_idx = base + 128 + __ffs(m4) - 1;
                else if (m5) first_idx = base + 160 + __ffs(m5) - 1;
                else if (m6) first_idx = base + 192 + __ffs(m6) - 1;
                else         first_idx = base + 224 + __ffs(m7) - 1;
            }
            int cum = have;
            const unsigned ms[8] = {m0, m1, m2, m3, m4, m5, m6, m7};
            #pragma unroll
            for (int k = 0; k < 8; k++) {
                const int s = cum + __popc(ms[k] & below);
                if ((ms[k] & mybit) && s < Kk) o[s] = (float)(base + 32 * k + lane);
                cum += __popc(ms[k]);
            }
            have = cum;
            if (have >= Kk) break;
        }
    }

    // Pad tail with group_first (warp-uniform value)
    const float fpad = (float)first_idx;
    for (int i = have + lane; i < Kk; i += 32) o[i] = fpad;
}

extern "C" void kernel_launch(void* const* d_in, const int* in_sizes, int n_in,
                              void* d_out, int out_size) {
    (void)out_size;
    const float* pos = nullptr;
    const int* centroids = nullptr;
    for (int i = 0; i < n_in; i++) {
        if (in_sizes[i] == Bb * Nn * 3)      pos = (const float*)d_in[i];
        else if (in_sizes[i] == Bb * Ss)     centroids = (const int*)d_in[i];
    }
    float* out = (float*)d_out;

    soa_transpose_kernel<<<(TP_THREADS + 255) / 256, 256>>>((const float4*)pos);

    const int total_warps = TOTAL;             // 16384
    const int threads = 64;                    // 2 warps/block (proven R12 shape)
    const int blocks = total_warps / 2;        // 8192
    gridgcn_knn_kernel<<<blocks, threads>>>(centroids, out);
}